// round 1
// baseline (speedup 1.0000x reference)
#include <cuda_runtime.h>
#include <math.h>

#define B_ 4
#define T_ 2048
#define C_ 1024
#define H_ 16
#define D_ 64
#define C3_ (3 * C_)
#define M_ (B_ * T_)

// Scratch (no cudaMalloc allowed)
__device__ float g_kqv[(size_t)M_ * C3_];   // [B*T, 3C]  k|q|v
__device__ float g_y[(size_t)M_ * C_];      // [B*T, C]   attention output (token-major, head-concat)

// ---------------------------------------------------------------------------
// SGEMM: C[M,N] = A[M,K] @ B[K,N] + bias[N]   (row-major, all dims % tile == 0)
// 128x128 tile, BK=8, 256 threads, 8x8 per thread.
// ---------------------------------------------------------------------------
#define BM 128
#define BN 128
#define BK 8
#define TM 8
#define TN 8

__global__ void __launch_bounds__(256) sgemm_bias(
    const float* __restrict__ A, const float* __restrict__ Bm,
    const float* __restrict__ bias, float* __restrict__ Cout,
    int M, int N, int K)
{
    __shared__ float As[BK][BM];
    __shared__ float Bs[BK][BN];

    const int bx = blockIdx.x;   // N tile
    const int by = blockIdx.y;   // M tile
    const int tid = threadIdx.x; // 0..255
    const int tx = tid % 16;
    const int ty = tid / 16;

    // A loads: 128 rows x 8 k, 4 floats/thread
    const int aRow = tid >> 1;          // 0..127
    const int aCol = (tid & 1) * 4;     // 0 or 4
    // B loads: 8 rows x 128 cols, 4 floats/thread
    const int bRow = tid >> 5;          // 0..7
    const int bCol = (tid & 31) * 4;    // 0..124

    const float* Aptr = A + (size_t)(by * BM + aRow) * K + aCol;
    const float* Bptr = Bm + (size_t)bRow * N + bx * BN + bCol;

    float acc[TM][TN];
    #pragma unroll
    for (int i = 0; i < TM; i++)
        #pragma unroll
        for (int j = 0; j < TN; j++) acc[i][j] = 0.f;

    for (int k0 = 0; k0 < K; k0 += BK) {
        float4 a4 = *(const float4*)(Aptr + k0);
        As[aCol + 0][aRow] = a4.x;
        As[aCol + 1][aRow] = a4.y;
        As[aCol + 2][aRow] = a4.z;
        As[aCol + 3][aRow] = a4.w;
        *(float4*)&Bs[bRow][bCol] = *(const float4*)(Bptr + (size_t)k0 * N);
        __syncthreads();

        #pragma unroll
        for (int kk = 0; kk < BK; kk++) {
            float4 a0 = *(const float4*)&As[kk][ty * TM];
            float4 a1 = *(const float4*)&As[kk][ty * TM + 4];
            float4 b0 = *(const float4*)&Bs[kk][tx * TN];
            float4 b1 = *(const float4*)&Bs[kk][tx * TN + 4];
            float ar[TM] = {a0.x, a0.y, a0.z, a0.w, a1.x, a1.y, a1.z, a1.w};
            float br[TN] = {b0.x, b0.y, b0.z, b0.w, b1.x, b1.y, b1.z, b1.w};
            #pragma unroll
            for (int i = 0; i < TM; i++)
                #pragma unroll
                for (int j = 0; j < TN; j++)
                    acc[i][j] += ar[i] * br[j];
        }
        __syncthreads();
    }

    #pragma unroll
    for (int i = 0; i < TM; i++) {
        const int row = by * BM + ty * TM + i;
        const int colbase = bx * BN + tx * TN;
        #pragma unroll
        for (int j = 0; j < TN; j += 4) {
            float4 o;
            o.x = acc[i][j + 0] + bias[colbase + j + 0];
            o.y = acc[i][j + 1] + bias[colbase + j + 1];
            o.z = acc[i][j + 2] + bias[colbase + j + 2];
            o.w = acc[i][j + 3] + bias[colbase + j + 3];
            *(float4*)&Cout[(size_t)row * N + colbase + j] = o;
        }
    }
}

// ---------------------------------------------------------------------------
// Flash attention (fp32, causal, padding mask).
// 64 threads/block, 1 query row/thread. Tiles of 64 keys, only kt <= qt.
// kqv layout per token row (stride 3C): [k(0:C) | q(C:2C) | v(2C:3C)], head h at h*D.
// ---------------------------------------------------------------------------
#define BQ 64
#define BKV 64

__global__ void __launch_bounds__(BQ) flash_attn(
    const float* __restrict__ kqv, const int* __restrict__ pmask,
    float* __restrict__ y)
{
    const int qt = blockIdx.x;          // query tile 0..T/BQ-1
    const int bh = blockIdx.y;          // 0..B*H-1
    const int b  = bh / H_;
    const int h  = bh % H_;
    const int t  = threadIdx.x;         // 0..63
    const int qg = qt * BQ + t;         // global query index within sequence

    const float* base = kqv + (size_t)b * T_ * C3_ + h * D_;

    // q row -> registers (16 float4)
    float4 q[16];
    {
        const float4* qrow = (const float4*)(base + (size_t)qg * C3_ + C_);
        #pragma unroll
        for (int i = 0; i < 16; i++) q[i] = qrow[i];
    }

    float4 acc[16];
    #pragma unroll
    for (int i = 0; i < 16; i++) acc[i] = make_float4(0.f, 0.f, 0.f, 0.f);
    float m = -INFINITY, l = 0.f;

    __shared__ float4 KVsh[BKV * 16];      // 16 KB, reused K then V
    __shared__ float  Ssh[BQ][BKV + 1];    // padded: no bank conflicts
    __shared__ int    pmsh[BKV];

    const int* pmrow = pmask + b * T_;
    const int d4 = t & 15;     // load lane
    const int jr = t >> 4;

    for (int kt = 0; kt <= qt; kt++) {
        const int kbase = kt * BKV;

        // ---- load K tile (coalesced: 16 threads x 16B contiguous) ----
        {
            const float* Kg = base + (size_t)kbase * C3_;   // k part offset 0
            #pragma unroll
            for (int jj = 0; jj < BKV; jj += 4) {
                int j = jj + jr;
                KVsh[j * 16 + d4] = *(const float4*)(Kg + (size_t)j * C3_ + d4 * 4);
            }
            pmsh[t] = pmrow[kbase + t];
        }
        __syncthreads();

        // ---- pass 1: S row + tile max ----
        float mt = -INFINITY;
        const bool diag = (kt == qt);
        #pragma unroll 4
        for (int j = 0; j < BKV; j++) {
            float s0 = 0.f, s1 = 0.f, s2 = 0.f, s3 = 0.f;
            #pragma unroll
            for (int dd = 0; dd < 16; dd++) {
                float4 kv = KVsh[j * 16 + dd];
                s0 += q[dd].x * kv.x;
                s1 += q[dd].y * kv.y;
                s2 += q[dd].z * kv.z;
                s3 += q[dd].w * kv.w;
            }
            float s = ((s0 + s1) + (s2 + s3)) * 0.125f;  // 1/sqrt(64)
            bool ok = (!diag || (j <= t)) && (pmsh[j] != 0);
            s = ok ? s : -INFINITY;
            Ssh[t][j] = s;
            mt = fmaxf(mt, s);
        }

        float mnew = fmaxf(m, mt);
        float msafe = (mnew == -INFINITY) ? 0.f : mnew;
        float corr = __expf(m - msafe);       // 0 when m == -inf
        l *= corr;
        #pragma unroll
        for (int i = 0; i < 16; i++) {
            acc[i].x *= corr; acc[i].y *= corr;
            acc[i].z *= corr; acc[i].w *= corr;
        }
        m = mnew;
        __syncthreads();   // pass1 done reading K

        // ---- load V tile into same buffer ----
        {
            const float* Vg = base + (size_t)kbase * C3_ + 2 * C_;
            #pragma unroll
            for (int jj = 0; jj < BKV; jj += 4) {
                int j = jj + jr;
                KVsh[j * 16 + d4] = *(const float4*)(Vg + (size_t)j * C3_ + d4 * 4);
            }
        }
        __syncthreads();

        // ---- pass 2: softmax + PV ----
        #pragma unroll 2
        for (int j = 0; j < BKV; j++) {
            float p = __expf(Ssh[t][j] - msafe);
            l += p;
            #pragma unroll
            for (int dd = 0; dd < 16; dd++) {
                float4 vv = KVsh[j * 16 + dd];
                acc[dd].x += p * vv.x;
                acc[dd].y += p * vv.y;
                acc[dd].z += p * vv.z;
                acc[dd].w += p * vv.w;
            }
        }
        __syncthreads();   // before next K load overwrites KVsh
    }

    const float inv = 1.f / l;
    float* yrow = y + ((size_t)b * T_ + qg) * C_ + h * D_;
    #pragma unroll
    for (int i = 0; i < 16; i++) {
        float4 o = acc[i];
        o.x *= inv; o.y *= inv; o.z *= inv; o.w *= inv;
        ((float4*)yrow)[i] = o;
    }
}

// ---------------------------------------------------------------------------
extern "C" void kernel_launch(void* const* d_in, const int* in_sizes, int n_in,
                              void* d_out, int out_size)
{
    const float* x      = (const float*)d_in[0];   // [B,T,C]
    const float* W_kqv  = (const float*)d_in[1];   // [C,3C]
    const float* b_kqv  = (const float*)d_in[2];   // [3C]
    const float* W_proj = (const float*)d_in[3];   // [C,C]
    const float* b_proj = (const float*)d_in[4];   // [C]
    const int*   pmask  = (const int*)d_in[5];     // [B,T]
    float* out = (float*)d_out;                    // [B,T,C]

    float* kqv_ptr = nullptr;
    float* y_ptr = nullptr;
    cudaGetSymbolAddress((void**)&kqv_ptr, g_kqv);
    cudaGetSymbolAddress((void**)&y_ptr, g_y);

    // 1) kqv = x @ W_kqv + b_kqv
    {
        dim3 grid(C3_ / BN, M_ / BM);
        sgemm_bias<<<grid, 256>>>(x, W_kqv, b_kqv, kqv_ptr, M_, C3_, C_);
    }
    // 2) flash attention
    {
        dim3 grid(T_ / BQ, B_ * H_);
        flash_attn<<<grid, BQ>>>(kqv_ptr, pmask, y_ptr);
    }
    // 3) out = y @ W_proj + b_proj
    {
        dim3 grid(C_ / BN, M_ / BM);
        sgemm_bias<<<grid, 256>>>(y_ptr, W_proj, b_proj, out, M_, C_, C_);
    }
}

// round 3
// speedup vs baseline: 1.4547x; 1.4547x over previous
#include <cuda_runtime.h>
#include <math.h>
#include <stdint.h>

#define B_ 4
#define T_ 2048
#define C_ 1024
#define H_ 16
#define D_ 64
#define C3_ (3 * C_)
#define M_ (B_ * T_)

// ---------------------------------------------------------------------------
// Scratch (no cudaMalloc allowed)
// ---------------------------------------------------------------------------
__device__ float g_xa[(size_t)M_ * C_];       // x rounded to tf32
__device__ float g_wkqvT[(size_t)C3_ * C_];   // W_kqv^T [3C, C], tf32-rounded
__device__ float g_wprojT[(size_t)C_ * C_];   // W_proj^T [C, C], tf32-rounded
__device__ float g_kqv[(size_t)M_ * C3_];     // [B*T, 3C]  k|q|v (fp32)
__device__ float g_y[(size_t)M_ * C_];        // attention out (tf32-rounded)

__device__ __forceinline__ float tf32r(float v) {
    float o;
    asm("cvt.rna.tf32.f32 %0, %1;" : "=f"(o) : "f"(v));
    return o;
}

// mma.sync m16n8k8 tf32: D = A*B + C (fp32 accum)
__device__ __forceinline__ void mma_tf32(
    float c[4], uint32_t a0, uint32_t a1, uint32_t a2, uint32_t a3,
    uint32_t b0, uint32_t b1)
{
    asm volatile(
        "mma.sync.aligned.m16n8k8.row.col.f32.tf32.tf32.f32 "
        "{%0,%1,%2,%3}, {%4,%5,%6,%7}, {%8,%9}, {%0,%1,%2,%3};"
        : "+f"(c[0]), "+f"(c[1]), "+f"(c[2]), "+f"(c[3])
        : "r"(a0), "r"(a1), "r"(a2), "r"(a3), "r"(b0), "r"(b1));
}

// ---------------------------------------------------------------------------
// tf32 round (elementwise, vectorized)
// ---------------------------------------------------------------------------
__global__ void __launch_bounds__(256) round_tf32_vec(
    const float* __restrict__ in, float* __restrict__ out, int n4)
{
    int i = blockIdx.x * blockDim.x + threadIdx.x;
    if (i >= n4) return;
    float4 v = ((const float4*)in)[i];
    v.x = tf32r(v.x); v.y = tf32r(v.y); v.z = tf32r(v.z); v.w = tf32r(v.w);
    ((float4*)out)[i] = v;
}

// ---------------------------------------------------------------------------
// Transpose + tf32-round: W [K,N] -> Wt [N,K]
// ---------------------------------------------------------------------------
__global__ void __launch_bounds__(256) transpose_round(
    const float* __restrict__ W, float* __restrict__ Wt, int K, int N)
{
    __shared__ float tile[32][33];
    const int n0 = blockIdx.x * 32, k0 = blockIdx.y * 32;
    #pragma unroll
    for (int i = threadIdx.y; i < 32; i += 8)
        tile[i][threadIdx.x] = W[(size_t)(k0 + i) * N + n0 + threadIdx.x];
    __syncthreads();
    #pragma unroll
    for (int i = threadIdx.y; i < 32; i += 8)
        Wt[(size_t)(n0 + i) * K + k0 + threadIdx.x] = tf32r(tile[threadIdx.x][i]);
}

// ---------------------------------------------------------------------------
// tf32 tensor-core GEMM via mma.sync:
//   C[M,N] = A[M,K] @ Bt[N,K]^T + bias[N]
// CTA tile 128x128, BK=32, 256 threads (8 warps, 2x4), warp tile 64x32.
// A, Bt pre-rounded to tf32.
// ---------------------------------------------------------------------------
#define GBM 128
#define GBN 128
#define GBK 32
#define SPITCH 36   // 32 + 4 float pad; 144B row pitch keeps float4 alignment

__global__ void __launch_bounds__(256, 2) gemm_tf32_mma(
    const float* __restrict__ A, const float* __restrict__ Bt,
    const float* __restrict__ bias, float* __restrict__ Cout,
    int M, int N, int K)
{
    __shared__ float As[GBM * SPITCH];
    __shared__ float Bs[GBN * SPITCH];

    const int tid = threadIdx.x;
    const int wid = tid >> 5;
    const int lane = tid & 31;
    const int g = lane >> 2;       // group row 0..7
    const int q = lane & 3;        // quad col 0..3

    const int wm = (wid >> 2) * 64;    // warp M offset: 0 or 64
    const int wn = (wid & 3) * 32;     // warp N offset: 0,32,64,96

    const int mtile = blockIdx.y;
    const int ntile = blockIdx.x;

    const float* Ag = A + (size_t)mtile * GBM * K;
    const float* Bg = Bt + (size_t)ntile * GBN * K;

    // global load mapping: 1024 float4 per tile, 4 per thread
    // idx = tid + i*256; row = idx>>3 (0..127); c4 = idx&7
    float4 pa[4], pb[4];
    #pragma unroll
    for (int i = 0; i < 4; i++) {
        const int idx = tid + i * 256;
        const int row = idx >> 3, c4 = idx & 7;
        pa[i] = *(const float4*)(Ag + (size_t)row * K + c4 * 4);
        pb[i] = *(const float4*)(Bg + (size_t)row * K + c4 * 4);
    }

    float acc[4][4][4];
    #pragma unroll
    for (int mi = 0; mi < 4; mi++)
        #pragma unroll
        for (int ni = 0; ni < 4; ni++)
            #pragma unroll
            for (int r = 0; r < 4; r++) acc[mi][ni][r] = 0.f;

    const int nchunk = K / GBK;
    for (int ch = 0; ch < nchunk; ch++) {
        // store staged regs to smem
        #pragma unroll
        for (int i = 0; i < 4; i++) {
            const int idx = tid + i * 256;
            const int row = idx >> 3, c4 = idx & 7;
            *(float4*)&As[row * SPITCH + c4 * 4] = pa[i];
            *(float4*)&Bs[row * SPITCH + c4 * 4] = pb[i];
        }
        __syncthreads();

        // prefetch next chunk
        if (ch + 1 < nchunk) {
            const int k0 = (ch + 1) * GBK;
            #pragma unroll
            for (int i = 0; i < 4; i++) {
                const int idx = tid + i * 256;
                const int row = idx >> 3, c4 = idx & 7;
                pa[i] = *(const float4*)(Ag + (size_t)row * K + k0 + c4 * 4);
                pb[i] = *(const float4*)(Bg + (size_t)row * K + k0 + c4 * 4);
            }
        }

        // compute: 4 k-steps of 8
        #pragma unroll
        for (int ks = 0; ks < GBK; ks += 8) {
            uint32_t af[4][4], bf[4][2];
            #pragma unroll
            for (int mi = 0; mi < 4; mi++) {
                const int m0 = wm + mi * 16;
                af[mi][0] = __float_as_uint(As[(m0 + g) * SPITCH + ks + q]);
                af[mi][1] = __float_as_uint(As[(m0 + 8 + g) * SPITCH + ks + q]);
                af[mi][2] = __float_as_uint(As[(m0 + g) * SPITCH + ks + q + 4]);
                af[mi][3] = __float_as_uint(As[(m0 + 8 + g) * SPITCH + ks + q + 4]);
            }
            #pragma unroll
            for (int ni = 0; ni < 4; ni++) {
                const int n0 = wn + ni * 8;
                bf[ni][0] = __float_as_uint(Bs[(n0 + g) * SPITCH + ks + q]);
                bf[ni][1] = __float_as_uint(Bs[(n0 + g) * SPITCH + ks + q + 4]);
            }
            #pragma unroll
            for (int mi = 0; mi < 4; mi++)
                #pragma unroll
                for (int ni = 0; ni < 4; ni++)
                    mma_tf32(acc[mi][ni], af[mi][0], af[mi][1], af[mi][2], af[mi][3],
                             bf[ni][0], bf[ni][1]);
        }
        __syncthreads();
    }

    // epilogue: c0,c1 -> (row g, cols 2q,2q+1); c2,c3 -> (row g+8)
    const int rowbase = mtile * GBM + wm;
    const int colbase = ntile * GBN + wn;
    #pragma unroll
    for (int mi = 0; mi < 4; mi++) {
        #pragma unroll
        for (int ni = 0; ni < 4; ni++) {
            const int col = colbase + ni * 8 + 2 * q;
            const float bx = bias[col], by = bias[col + 1];
            const int r0 = rowbase + mi * 16 + g;
            float2 v0 = make_float2(acc[mi][ni][0] + bx, acc[mi][ni][1] + by);
            float2 v1 = make_float2(acc[mi][ni][2] + bx, acc[mi][ni][3] + by);
            *(float2*)(Cout + (size_t)r0 * N + col) = v0;
            *(float2*)(Cout + (size_t)(r0 + 8) * N + col) = v1;
        }
    }
}

// ---------------------------------------------------------------------------
// Flash attention (fp32, causal, padding mask). Output tf32-rounded.
// ---------------------------------------------------------------------------
#define BQ 64
#define BKV 64

__global__ void __launch_bounds__(BQ) flash_attn(
    const float* __restrict__ kqv, const int* __restrict__ pmask,
    float* __restrict__ y)
{
    const int qt = blockIdx.x;
    const int bh = blockIdx.y;
    const int b  = bh / H_;
    const int h  = bh % H_;
    const int t  = threadIdx.x;
    const int qg = qt * BQ + t;

    const float* base = kqv + (size_t)b * T_ * C3_ + h * D_;

    float4 q[16];
    {
        const float4* qrow = (const float4*)(base + (size_t)qg * C3_ + C_);
        #pragma unroll
        for (int i = 0; i < 16; i++) q[i] = qrow[i];
    }

    float4 acc[16];
    #pragma unroll
    for (int i = 0; i < 16; i++) acc[i] = make_float4(0.f, 0.f, 0.f, 0.f);
    float m = -INFINITY, l = 0.f;

    __shared__ float4 KVsh[BKV * 16];
    __shared__ float  Ssh[BQ][BKV + 1];
    __shared__ int    pmsh[BKV];

    const int* pmrow = pmask + b * T_;
    const int d4 = t & 15;
    const int jr = t >> 4;

    for (int kt = 0; kt <= qt; kt++) {
        const int kbase = kt * BKV;
        {
            const float* Kg = base + (size_t)kbase * C3_;
            #pragma unroll
            for (int jj = 0; jj < BKV; jj += 4) {
                int j = jj + jr;
                KVsh[j * 16 + d4] = *(const float4*)(Kg + (size_t)j * C3_ + d4 * 4);
            }
            pmsh[t] = pmrow[kbase + t];
        }
        __syncthreads();

        float mt = -INFINITY;
        const bool diag = (kt == qt);
        #pragma unroll 4
        for (int j = 0; j < BKV; j++) {
            float s0 = 0.f, s1 = 0.f, s2 = 0.f, s3 = 0.f;
            #pragma unroll
            for (int dd = 0; dd < 16; dd++) {
                float4 kv = KVsh[j * 16 + dd];
                s0 += q[dd].x * kv.x;
                s1 += q[dd].y * kv.y;
                s2 += q[dd].z * kv.z;
                s3 += q[dd].w * kv.w;
            }
            float s = ((s0 + s1) + (s2 + s3)) * 0.125f;
            bool ok = (!diag || (j <= t)) && (pmsh[j] != 0);
            s = ok ? s : -INFINITY;
            Ssh[t][j] = s;
            mt = fmaxf(mt, s);
        }

        float mnew = fmaxf(m, mt);
        float msafe = (mnew == -INFINITY) ? 0.f : mnew;
        float corr = __expf(m - msafe);
        l *= corr;
        #pragma unroll
        for (int i = 0; i < 16; i++) {
            acc[i].x *= corr; acc[i].y *= corr;
            acc[i].z *= corr; acc[i].w *= corr;
        }
        m = mnew;
        __syncthreads();

        {
            const float* Vg = base + (size_t)kbase * C3_ + 2 * C_;
            #pragma unroll
            for (int jj = 0; jj < BKV; jj += 4) {
                int j = jj + jr;
                KVsh[j * 16 + d4] = *(const float4*)(Vg + (size_t)j * C3_ + d4 * 4);
            }
        }
        __syncthreads();

        #pragma unroll 2
        for (int j = 0; j < BKV; j++) {
            float p = __expf(Ssh[t][j] - msafe);
            l += p;
            #pragma unroll
            for (int dd = 0; dd < 16; dd++) {
                float4 vv = KVsh[j * 16 + dd];
                acc[dd].x += p * vv.x;
                acc[dd].y += p * vv.y;
                acc[dd].z += p * vv.z;
                acc[dd].w += p * vv.w;
            }
        }
        __syncthreads();
    }

    const float inv = 1.f / l;
    float* yrow = y + ((size_t)b * T_ + qg) * C_ + h * D_;
    #pragma unroll
    for (int i = 0; i < 16; i++) {
        float4 o = acc[i];
        o.x = tf32r(o.x * inv); o.y = tf32r(o.y * inv);
        o.z = tf32r(o.z * inv); o.w = tf32r(o.w * inv);
        ((float4*)yrow)[i] = o;
    }
}

// ---------------------------------------------------------------------------
extern "C" void kernel_launch(void* const* d_in, const int* in_sizes, int n_in,
                              void* d_out, int out_size)
{
    const float* x      = (const float*)d_in[0];   // [B,T,C]
    const float* W_kqv  = (const float*)d_in[1];   // [C,3C]
    const float* b_kqv  = (const float*)d_in[2];   // [3C]
    const float* W_proj = (const float*)d_in[3];   // [C,C]
    const float* b_proj = (const float*)d_in[4];   // [C]
    const int*   pmask  = (const int*)d_in[5];     // [B,T]
    float* out = (float*)d_out;                    // [B,T,C]

    float *xa, *wkqvT, *wprojT, *kqv, *y;
    cudaGetSymbolAddress((void**)&xa, g_xa);
    cudaGetSymbolAddress((void**)&wkqvT, g_wkqvT);
    cudaGetSymbolAddress((void**)&wprojT, g_wprojT);
    cudaGetSymbolAddress((void**)&kqv, g_kqv);
    cudaGetSymbolAddress((void**)&y, g_y);

    // 0) tf32-round x; transpose+round weights
    {
        int n4 = M_ * C_ / 4;
        round_tf32_vec<<<(n4 + 255) / 256, 256>>>(x, xa, n4);
        dim3 g1(C3_ / 32, C_ / 32);
        transpose_round<<<g1, dim3(32, 8)>>>(W_kqv, wkqvT, C_, C3_);
        dim3 g2(C_ / 32, C_ / 32);
        transpose_round<<<g2, dim3(32, 8)>>>(W_proj, wprojT, C_, C_);
    }
    // 1) kqv = xa @ W_kqv + b_kqv   (tensor cores, tf32 mma.sync)
    {
        dim3 grid(C3_ / GBN, M_ / GBM);
        gemm_tf32_mma<<<grid, 256>>>(xa, wkqvT, b_kqv, kqv, M_, C3_, C_);
    }
    // 2) flash attention (fp32)
    {
        dim3 grid(T_ / BQ, B_ * H_);
        flash_attn<<<grid, BQ>>>(kqv, pmask, y);
    }
    // 3) out = y @ W_proj + b_proj  (tensor cores, tf32 mma.sync)
    {
        dim3 grid(C_ / GBN, M_ / GBM);
        gemm_tf32_mma<<<grid, 256>>>(y, wprojT, b_proj, out, M_, C_, C_);
    }
}

// round 5
// speedup vs baseline: 3.4920x; 2.4005x over previous
#include <cuda_runtime.h>
#include <math.h>
#include <stdint.h>

#define B_ 4
#define T_ 2048
#define C_ 1024
#define H_ 16
#define D_ 64
#define C3_ (3 * C_)
#define M_ (B_ * T_)

// ---------------------------------------------------------------------------
// Scratch (no cudaMalloc allowed)
// ---------------------------------------------------------------------------
__device__ float g_xa[(size_t)M_ * C_];       // x rounded to tf32
__device__ float g_wkqvT[(size_t)C3_ * C_];   // W_kqv^T [3C, C], tf32-rounded
__device__ float g_wprojT[(size_t)C_ * C_];   // W_proj^T [C, C], tf32-rounded
__device__ float g_kqv[(size_t)M_ * C3_];     // [B*T, 3C]  k|q|v (tf32-rounded)
__device__ float g_y[(size_t)M_ * C_];        // attention out (tf32-rounded)

__device__ __forceinline__ float tf32r(float v) {
    float o;
    asm("cvt.rna.tf32.f32 %0, %1;" : "=f"(o) : "f"(v));
    return o;
}

// mma.sync m16n8k8 tf32: D = A*B + C (fp32 accum)
__device__ __forceinline__ void mma_tf32(
    float c[4], uint32_t a0, uint32_t a1, uint32_t a2, uint32_t a3,
    uint32_t b0, uint32_t b1)
{
    asm volatile(
        "mma.sync.aligned.m16n8k8.row.col.f32.tf32.tf32.f32 "
        "{%0,%1,%2,%3}, {%4,%5,%6,%7}, {%8,%9}, {%0,%1,%2,%3};"
        : "+f"(c[0]), "+f"(c[1]), "+f"(c[2]), "+f"(c[3])
        : "r"(a0), "r"(a1), "r"(a2), "r"(a3), "r"(b0), "r"(b1));
}

// ---------------------------------------------------------------------------
// tf32 round (elementwise, vectorized)
// ---------------------------------------------------------------------------
__global__ void __launch_bounds__(256) round_tf32_vec(
    const float* __restrict__ in, float* __restrict__ out, int n4)
{
    int i = blockIdx.x * blockDim.x + threadIdx.x;
    if (i >= n4) return;
    float4 v = ((const float4*)in)[i];
    v.x = tf32r(v.x); v.y = tf32r(v.y); v.z = tf32r(v.z); v.w = tf32r(v.w);
    ((float4*)out)[i] = v;
}

// ---------------------------------------------------------------------------
// Transpose + tf32-round: W [K,N] -> Wt [N,K]
// ---------------------------------------------------------------------------
__global__ void __launch_bounds__(256) transpose_round(
    const float* __restrict__ W, float* __restrict__ Wt, int K, int N)
{
    __shared__ float tile[32][33];
    const int n0 = blockIdx.x * 32, k0 = blockIdx.y * 32;
    #pragma unroll
    for (int i = threadIdx.y; i < 32; i += 8)
        tile[i][threadIdx.x] = W[(size_t)(k0 + i) * N + n0 + threadIdx.x];
    __syncthreads();
    #pragma unroll
    for (int i = threadIdx.y; i < 32; i += 8)
        Wt[(size_t)(n0 + i) * K + k0 + threadIdx.x] = tf32r(tile[threadIdx.x][i]);
}

// ---------------------------------------------------------------------------
// tf32 tensor-core GEMM via mma.sync:
//   C[M,N] = A[M,K] @ Bt[N,K]^T + bias[N]   (optionally tf32-round the output)
// CTA tile 128x128, BK=32, 256 threads (8 warps, 2x4), warp tile 64x32.
// ---------------------------------------------------------------------------
#define GBM 128
#define GBN 128
#define GBK 32
#define SPITCH 36   // 32 + 4 float pad (32-wide chunks -> pitch 36 is correct HERE)

__global__ void __launch_bounds__(256, 2) gemm_tf32_mma(
    const float* __restrict__ A, const float* __restrict__ Bt,
    const float* __restrict__ bias, float* __restrict__ Cout,
    int M, int N, int K, int roundOut)
{
    __shared__ float As[GBM * SPITCH];
    __shared__ float Bs[GBN * SPITCH];

    const int tid = threadIdx.x;
    const int wid = tid >> 5;
    const int lane = tid & 31;
    const int g = lane >> 2;
    const int q = lane & 3;

    const int wm = (wid >> 2) * 64;
    const int wn = (wid & 3) * 32;

    const int mtile = blockIdx.y;
    const int ntile = blockIdx.x;

    const float* Ag = A + (size_t)mtile * GBM * K;
    const float* Bg = Bt + (size_t)ntile * GBN * K;

    float4 pa[4], pb[4];
    #pragma unroll
    for (int i = 0; i < 4; i++) {
        const int idx = tid + i * 256;
        const int row = idx >> 3, c4 = idx & 7;
        pa[i] = *(const float4*)(Ag + (size_t)row * K + c4 * 4);
        pb[i] = *(const float4*)(Bg + (size_t)row * K + c4 * 4);
    }

    float acc[4][4][4];
    #pragma unroll
    for (int mi = 0; mi < 4; mi++)
        #pragma unroll
        for (int ni = 0; ni < 4; ni++)
            #pragma unroll
            for (int r = 0; r < 4; r++) acc[mi][ni][r] = 0.f;

    const int nchunk = K / GBK;
    for (int ch = 0; ch < nchunk; ch++) {
        #pragma unroll
        for (int i = 0; i < 4; i++) {
            const int idx = tid + i * 256;
            const int row = idx >> 3, c4 = idx & 7;
            *(float4*)&As[row * SPITCH + c4 * 4] = pa[i];
            *(float4*)&Bs[row * SPITCH + c4 * 4] = pb[i];
        }
        __syncthreads();

        if (ch + 1 < nchunk) {
            const int k0 = (ch + 1) * GBK;
            #pragma unroll
            for (int i = 0; i < 4; i++) {
                const int idx = tid + i * 256;
                const int row = idx >> 3, c4 = idx & 7;
                pa[i] = *(const float4*)(Ag + (size_t)row * K + k0 + c4 * 4);
                pb[i] = *(const float4*)(Bg + (size_t)row * K + k0 + c4 * 4);
            }
        }

        #pragma unroll
        for (int ks = 0; ks < GBK; ks += 8) {
            uint32_t af[4][4], bf[4][2];
            #pragma unroll
            for (int mi = 0; mi < 4; mi++) {
                const int mo = wm + mi * 16;
                af[mi][0] = __float_as_uint(As[(mo + g) * SPITCH + ks + q]);
                af[mi][1] = __float_as_uint(As[(mo + 8 + g) * SPITCH + ks + q]);
                af[mi][2] = __float_as_uint(As[(mo + g) * SPITCH + ks + q + 4]);
                af[mi][3] = __float_as_uint(As[(mo + 8 + g) * SPITCH + ks + q + 4]);
            }
            #pragma unroll
            for (int ni = 0; ni < 4; ni++) {
                const int no = wn + ni * 8;
                bf[ni][0] = __float_as_uint(Bs[(no + g) * SPITCH + ks + q]);
                bf[ni][1] = __float_as_uint(Bs[(no + g) * SPITCH + ks + q + 4]);
            }
            #pragma unroll
            for (int mi = 0; mi < 4; mi++)
                #pragma unroll
                for (int ni = 0; ni < 4; ni++)
                    mma_tf32(acc[mi][ni], af[mi][0], af[mi][1], af[mi][2], af[mi][3],
                             bf[ni][0], bf[ni][1]);
        }
        __syncthreads();
    }

    const int rowbase = mtile * GBM + wm;
    const int colbase = ntile * GBN + wn;
    #pragma unroll
    for (int mi = 0; mi < 4; mi++) {
        #pragma unroll
        for (int ni = 0; ni < 4; ni++) {
            const int col = colbase + ni * 8 + 2 * q;
            const float bx = bias[col], by = bias[col + 1];
            const int r0 = rowbase + mi * 16 + g;
            float2 v0 = make_float2(acc[mi][ni][0] + bx, acc[mi][ni][1] + by);
            float2 v1 = make_float2(acc[mi][ni][2] + bx, acc[mi][ni][3] + by);
            if (roundOut) {
                v0.x = tf32r(v0.x); v0.y = tf32r(v0.y);
                v1.x = tf32r(v1.x); v1.y = tf32r(v1.y);
            }
            *(float2*)(Cout + (size_t)r0 * N + col) = v0;
            *(float2*)(Cout + (size_t)(r0 + 8) * N + col) = v1;
        }
    }
}

// ---------------------------------------------------------------------------
// Tensor-core flash attention (tf32 mma.sync), causal + padding mask.
// CTA: 64 queries x one (b,h). 4 warps, each owns 16 query rows.
// Tiles are 64 floats wide (D=64, FKV=64) -> pitch 68 (== 4 mod 32,
// conflict-free fragment reads). K buffer reused for V (48KB static limit).
// ---------------------------------------------------------------------------
#define FBQ 64
#define FKV 64
#define KP  68   // 64 + 4 pad

__global__ void __launch_bounds__(128) flash_attn_tc(
    const float* __restrict__ kqv, const int* __restrict__ pmask,
    float* __restrict__ y)
{
    __shared__ float KVsh[FKV * KP];   // K tile, then reused for V
    __shared__ float PQsh[FBQ * KP];   // Q tile first, then reused for P
    __shared__ int   pm_sh[FKV];

    const int qt = (T_ / FBQ - 1) - blockIdx.x;   // long CTAs first
    const int bh = blockIdx.y;
    const int b  = bh / H_;
    const int h  = bh % H_;
    const int tid = threadIdx.x;
    const int wid = tid >> 5, lane = tid & 31;
    const int g = lane >> 2, q = lane & 3;
    const int m0 = wid * 16;

    const float* base = kqv + (size_t)b * T_ * C3_ + h * D_;
    const int* pmrow = pmask + b * T_;

    // ---- load Q tile (scaled by 1/sqrt(D)=0.125, exact in tf32) ----
    {
        const float* Qg = base + C_;
        #pragma unroll
        for (int it = 0; it < 8; it++) {
            int idx = tid + it * 128;
            int r = idx >> 4, c4 = idx & 15;
            float4 v = *(const float4*)(Qg + (size_t)(qt * FBQ + r) * C3_ + c4 * 4);
            v.x *= 0.125f; v.y *= 0.125f; v.z *= 0.125f; v.w *= 0.125f;
            *(float4*)&PQsh[r * KP + c4 * 4] = v;
        }
    }
    __syncthreads();

    // ---- Q fragments to registers (held whole kernel) ----
    uint32_t qf[8][4];
    #pragma unroll
    for (int kk = 0; kk < 8; kk++) {
        qf[kk][0] = __float_as_uint(PQsh[(m0 + g) * KP + kk * 8 + q]);
        qf[kk][1] = __float_as_uint(PQsh[(m0 + 8 + g) * KP + kk * 8 + q]);
        qf[kk][2] = __float_as_uint(PQsh[(m0 + g) * KP + kk * 8 + q + 4]);
        qf[kk][3] = __float_as_uint(PQsh[(m0 + 8 + g) * KP + kk * 8 + q + 4]);
    }
    __syncthreads();

    float o[8][4];
    #pragma unroll
    for (int ni = 0; ni < 8; ni++)
        #pragma unroll
        for (int r = 0; r < 4; r++) o[ni][r] = 0.f;

    float mr0 = -INFINITY, mr1 = -INFINITY;   // running row max (rows g, g+8)
    float l0 = 0.f, l1 = 0.f;                 // lane-partial row sums

    const int r0g = qt * FBQ + m0 + g;        // global query rows
    const int r1g = r0g + 8;

    for (int kt = 0; kt <= qt; kt++) {
        const int kbase = kt * FKV;

        // ---- load K tile ----
        #pragma unroll
        for (int it = 0; it < 8; it++) {
            int idx = tid + it * 128;
            int r = idx >> 4, c4 = idx & 15;
            const float* rowp = base + (size_t)(kbase + r) * C3_;
            *(float4*)&KVsh[r * KP + c4 * 4] = *(const float4*)(rowp + c4 * 4);
        }
        if (tid < FKV) pm_sh[tid] = pmrow[kbase + tid];
        __syncthreads();

        // ---- S = Q K^T (per-warp 16x64) ----
        float s[8][4];
        #pragma unroll
        for (int ni = 0; ni < 8; ni++)
            #pragma unroll
            for (int r = 0; r < 4; r++) s[ni][r] = 0.f;

        #pragma unroll
        for (int kk = 0; kk < 8; kk++) {
            #pragma unroll
            for (int ni = 0; ni < 8; ni++) {
                uint32_t b0 = __float_as_uint(KVsh[(ni * 8 + g) * KP + kk * 8 + q]);
                uint32_t b1 = __float_as_uint(KVsh[(ni * 8 + g) * KP + kk * 8 + q + 4]);
                mma_tf32(s[ni], qf[kk][0], qf[kk][1], qf[kk][2], qf[kk][3], b0, b1);
            }
        }
        __syncthreads();   // K reads done; KVsh free for V

        // ---- load V tile into KVsh (overlaps with softmax below) ----
        #pragma unroll
        for (int it = 0; it < 8; it++) {
            int idx = tid + it * 128;
            int r = idx >> 4, c4 = idx & 15;
            const float* rowp = base + (size_t)(kbase + r) * C3_ + 2 * C_;
            *(float4*)&KVsh[r * KP + c4 * 4] = *(const float4*)(rowp + c4 * 4);
        }

        // ---- mask + tile max ----
        const bool diag = (kt == qt);
        float mt0 = -INFINITY, mt1 = -INFINITY;
        #pragma unroll
        for (int ni = 0; ni < 8; ni++) {
            const int c0 = ni * 8 + 2 * q, c1 = c0 + 1;
            const bool pm0 = pm_sh[c0] != 0, pm1 = pm_sh[c1] != 0;
            const int gc0 = kbase + c0, gc1 = kbase + c1;
            if (!(pm0 && (!diag || gc0 <= r0g))) s[ni][0] = -1e30f;
            if (!(pm1 && (!diag || gc1 <= r0g))) s[ni][1] = -1e30f;
            if (!(pm0 && (!diag || gc0 <= r1g))) s[ni][2] = -1e30f;
            if (!(pm1 && (!diag || gc1 <= r1g))) s[ni][3] = -1e30f;
            mt0 = fmaxf(mt0, fmaxf(s[ni][0], s[ni][1]));
            mt1 = fmaxf(mt1, fmaxf(s[ni][2], s[ni][3]));
        }
        mt0 = fmaxf(mt0, __shfl_xor_sync(0xffffffffu, mt0, 1));
        mt0 = fmaxf(mt0, __shfl_xor_sync(0xffffffffu, mt0, 2));
        mt1 = fmaxf(mt1, __shfl_xor_sync(0xffffffffu, mt1, 1));
        mt1 = fmaxf(mt1, __shfl_xor_sync(0xffffffffu, mt1, 2));

        const float mn0 = fmaxf(mr0, mt0), mn1 = fmaxf(mr1, mt1);
        const float ms0 = (mn0 < -1e29f) ? 0.f : mn0;
        const float ms1 = (mn1 < -1e29f) ? 0.f : mn1;
        const float corr0 = __expf(mr0 - ms0);   // 0 when mr0 == -inf
        const float corr1 = __expf(mr1 - ms1);
        mr0 = mn0; mr1 = mn1;
        l0 *= corr0; l1 *= corr1;
        #pragma unroll
        for (int ni = 0; ni < 8; ni++) {
            o[ni][0] *= corr0; o[ni][1] *= corr0;
            o[ni][2] *= corr1; o[ni][3] *= corr1;
        }

        // ---- P = exp(S - m), store tf32 to smem (own warp rows only) ----
        #pragma unroll
        for (int ni = 0; ni < 8; ni++) {
            float p0 = __expf(s[ni][0] - ms0);
            float p1 = __expf(s[ni][1] - ms0);
            float p2 = __expf(s[ni][2] - ms1);
            float p3 = __expf(s[ni][3] - ms1);
            l0 += p0 + p1; l1 += p2 + p3;
            *(float2*)&PQsh[(m0 + g) * KP + ni * 8 + 2 * q] =
                make_float2(tf32r(p0), tf32r(p1));
            *(float2*)&PQsh[(m0 + 8 + g) * KP + ni * 8 + 2 * q] =
                make_float2(tf32r(p2), tf32r(p3));
        }
        __syncthreads();   // V tile fully stored + P visible

        // ---- O += P V  (V read transposed from [keys][d] layout) ----
        #pragma unroll
        for (int kk = 0; kk < 8; kk++) {
            uint32_t a0 = __float_as_uint(PQsh[(m0 + g) * KP + kk * 8 + q]);
            uint32_t a1 = __float_as_uint(PQsh[(m0 + 8 + g) * KP + kk * 8 + q]);
            uint32_t a2 = __float_as_uint(PQsh[(m0 + g) * KP + kk * 8 + q + 4]);
            uint32_t a3 = __float_as_uint(PQsh[(m0 + 8 + g) * KP + kk * 8 + q + 4]);
            #pragma unroll
            for (int ni = 0; ni < 8; ni++) {
                uint32_t b0 = __float_as_uint(KVsh[(kk * 8 + q) * KP + ni * 8 + g]);
                uint32_t b1 = __float_as_uint(KVsh[(kk * 8 + q + 4) * KP + ni * 8 + g]);
                mma_tf32(o[ni], a0, a1, a2, a3, b0, b1);
            }
        }
        __syncthreads();   // PV done before next K load overwrites KVsh
    }

    // ---- finalize: full row sums, normalize, write y (tf32-rounded) ----
    l0 += __shfl_xor_sync(0xffffffffu, l0, 1);
    l0 += __shfl_xor_sync(0xffffffffu, l0, 2);
    l1 += __shfl_xor_sync(0xffffffffu, l1, 1);
    l1 += __shfl_xor_sync(0xffffffffu, l1, 2);
    const float inv0 = 1.f / l0, inv1 = 1.f / l1;

    float* yb = y + (size_t)b * T_ * C_ + h * D_;
    #pragma unroll
    for (int ni = 0; ni < 8; ni++) {
        const int col = ni * 8 + 2 * q;
        *(float2*)&yb[(size_t)r0g * C_ + col] =
            make_float2(tf32r(o[ni][0] * inv0), tf32r(o[ni][1] * inv0));
        *(float2*)&yb[(size_t)r1g * C_ + col] =
            make_float2(tf32r(o[ni][2] * inv1), tf32r(o[ni][3] * inv1));
    }
}

// ---------------------------------------------------------------------------
extern "C" void kernel_launch(void* const* d_in, const int* in_sizes, int n_in,
                              void* d_out, int out_size)
{
    const float* x      = (const float*)d_in[0];   // [B,T,C]
    const float* W_kqv  = (const float*)d_in[1];   // [C,3C]
    const float* b_kqv  = (const float*)d_in[2];   // [3C]
    const float* W_proj = (const float*)d_in[3];   // [C,C]
    const float* b_proj = (const float*)d_in[4];   // [C]
    const int*   pmask  = (const int*)d_in[5];     // [B,T]
    float* out = (float*)d_out;                    // [B,T,C]

    float *xa, *wkqvT, *wprojT, *kqv, *y;
    cudaGetSymbolAddress((void**)&xa, g_xa);
    cudaGetSymbolAddress((void**)&wkqvT, g_wkqvT);
    cudaGetSymbolAddress((void**)&wprojT, g_wprojT);
    cudaGetSymbolAddress((void**)&kqv, g_kqv);
    cudaGetSymbolAddress((void**)&y, g_y);

    // 0) tf32-round x; transpose+round weights
    {
        int n4 = M_ * C_ / 4;
        round_tf32_vec<<<(n4 + 255) / 256, 256>>>(x, xa, n4);
        dim3 g1(C3_ / 32, C_ / 32);
        transpose_round<<<g1, dim3(32, 8)>>>(W_kqv, wkqvT, C_, C3_);
        dim3 g2(C_ / 32, C_ / 32);
        transpose_round<<<g2, dim3(32, 8)>>>(W_proj, wprojT, C_, C_);
    }
    // 1) kqv = xa @ W_kqv + b_kqv   (tf32 mma.sync; output tf32-rounded)
    {
        dim3 grid(C3_ / GBN, M_ / GBM);
        gemm_tf32_mma<<<grid, 256>>>(xa, wkqvT, b_kqv, kqv, M_, C3_, C_, 1);
    }
    // 2) flash attention (tf32 mma.sync)
    {
        dim3 grid(T_ / FBQ, B_ * H_);
        flash_attn_tc<<<grid, 128>>>(kqv, pmask, y);
    }
    // 3) out = y @ W_proj + b_proj  (tf32 mma.sync; fp32 output)
    {
        dim3 grid(C_ / GBN, M_ / GBM);
        gemm_tf32_mma<<<grid, 256>>>(y, wprojT, b_proj, out, M_, C_, C_, 0);
    }
}